// round 5
// baseline (speedup 1.0000x reference)
#include <cuda_runtime.h>
#include <cstdint>
#include <math.h>

#define Bn 256
#define Sn 512
#define Hn 64
#define En 330
#define Tn 16
#define START_IX 14
#define STOP_IX 15
#define NROWS_TOTAL 20868

// ---- scratch (static device memory) ----
__device__ float g_WT[En * 512];                       // Wih transposed+concat [E][512]
__device__ float g_bias[512];
__device__ float g_proj[(size_t)NROWS_TOTAL * 512];    // projected tables  ~42.7MB
__device__ float g_h[2][(size_t)Sn * Bn * Hn];         // lstm hidden       2x33.5MB
__device__ float g_feats[(size_t)Sn * Bn * Tn];        // emissions         8.4MB

// ---- packed f32x2 helpers ----
__device__ __forceinline__ void fma2(unsigned long long& d, unsigned long long a,
                                     unsigned long long b) {
    asm("fma.rn.f32x2 %0, %1, %2, %0;" : "+l"(d) : "l"(a), "l"(b));
}
__device__ __forceinline__ unsigned long long pack2(float a, float b) {
    unsigned long long v;
    asm("mov.b64 %0, {%1,%2};" : "=l"(v) : "f"(a), "f"(b));
    return v;
}
__device__ __forceinline__ float2 unpack2(unsigned long long v) {
    float2 r;
    asm("mov.b64 {%0,%1}, %2;" : "=f"(r.x), "=f"(r.y) : "l"(v));
    return r;
}
__device__ __forceinline__ float tanhfast(float x) {
    float y;
    asm("tanh.approx.f32 %0, %1;" : "=f"(y) : "f"(x));
    return y;
}
__device__ __forceinline__ float sigfast(float x) {
    return fmaf(0.5f, tanhfast(0.5f * x), 0.5f);
}

// ---- K0: transpose Wih_f/Wih_b into [E][512] and fold biases ----
__global__ void prep_kernel(const float* __restrict__ Wf, const float* __restrict__ Wb,
                            const float* __restrict__ bihf, const float* __restrict__ bhhf,
                            const float* __restrict__ bihb, const float* __restrict__ bhhb) {
    int idx = blockIdx.x * blockDim.x + threadIdx.x;
    if (idx < En * 512) {
        int c = idx / 512, j = idx % 512;
        g_WT[idx] = (j < 256) ? Wf[j * En + c] : Wb[(j - 256) * En + c];
    }
    if (idx < 512) {
        g_bias[idx] = (idx < 256) ? (bihf[idx] + bhhf[idx]) : (bihb[idx - 256] + bhhb[idx - 256]);
    }
}

// ---- K1: project ALL embedding tables into g_proj (single launch) ----
__global__ __launch_bounds__(512)
void proj_all_kernel(const float* __restrict__ word, const float* __restrict__ flag,
                     const float* __restrict__ bound, const float* __restrict__ radical,
                     const float* __restrict__ pinyin) {
    const int bb = blockIdx.x;
    const float* emb;
    int nrows, width, segoff, base, r0;
    if (bb < 2500)      { emb = word;    nrows = 20000; width = 100; segoff = 0;   base = 0;     r0 = bb * 8; }
    else if (bb < 2508) { emb = flag;    nrows = 60;    width = 50;  segoff = 100; base = 20000; r0 = (bb - 2500) * 8; }
    else if (bb < 2509) { emb = bound;   nrows = 8;     width = 50;  segoff = 150; base = 20060; r0 = 0; }
    else if (bb < 2547) { emb = radical; nrows = 300;   width = 50;  segoff = 200; base = 20068; r0 = (bb - 2509) * 8; }
    else                { emb = pinyin;  nrows = 500;   width = 80;  segoff = 250; base = 20368; r0 = (bb - 2547) * 8; }

    const int j = threadIdx.x;             // output column 0..511
    __shared__ __align__(16) float es[8][112];
    for (int i = threadIdx.x; i < 8 * width; i += 512) {
        int rr = i / width, kk = i % width;
        es[rr][kk] = (r0 + rr < nrows) ? emb[(size_t)(r0 + rr) * width + kk] : 0.f;
    }
    __syncthreads();

    unsigned long long acc[8] = {0ull, 0ull, 0ull, 0ull, 0ull, 0ull, 0ull, 0ull};
    const int hw = width >> 1;
    for (int kk = 0; kk < hw; kk++) {
        float w0 = g_WT[(size_t)(segoff + 2 * kk) * 512 + j];
        float w1 = g_WT[(size_t)(segoff + 2 * kk + 1) * 512 + j];
        unsigned long long w2 = pack2(w0, w1);
#pragma unroll
        for (int r = 0; r < 8; r++) {
            unsigned long long h2 = *(const unsigned long long*)&es[r][2 * kk];
            fma2(acc[r], h2, w2);
        }
    }
#pragma unroll
    for (int r = 0; r < 8; r++) {
        if (r0 + r < nrows) {
            float2 u = unpack2(acc[r]);
            g_proj[(size_t)(base + r0 + r) * 512 + j] = u.x + u.y;
        }
    }
}

// ---- K3: fused gather+recurrence. grid (128,2), 256 thr, Bc=2, 2 CTAs/SM ----
// thread j -> cell k=j>>2, gate g=j&3, Whh row = g*64+k, proj col = dir*256+row.
// z exchange via quad shfl; h double-buffered in smem; ONE barrier per step.
__global__ __launch_bounds__(256, 2)
void lstm_kernel(const float* __restrict__ Whh_f, const float* __restrict__ Whh_b,
                 const float* __restrict__ h0, const float* __restrict__ c0,
                 const int* __restrict__ wi, const int* __restrict__ fi,
                 const int* __restrict__ bi, const int* __restrict__ ri,
                 const int* __restrict__ pi) {
    const int dir = blockIdx.y;
    const int b0 = blockIdx.x * 2;
    const float* __restrict__ Whh = dir ? Whh_b : Whh_f;
    float* __restrict__ hout = g_h[dir];
    const unsigned FULL = 0xFFFFFFFFu;

    const int j = threadIdx.x;
    const int k = j >> 2, g = j & 3;
    const int row = g * 64 + k;
    const int col = dir * 256 + row;

    // weight row, k-paired
    unsigned long long wp[32];
    {
        const ulonglong2* wrow = (const ulonglong2*)(Whh + row * 64);
#pragma unroll
        for (int q = 0; q < 16; q++) { ulonglong2 t2 = wrow[q]; wp[2 * q] = t2.x; wp[2 * q + 1] = t2.y; }
    }

    __shared__ __align__(16) float h_sh[2][2][64];

    float c = 0.f;
    if (g == 0) {
        c = c0[dir * Bn * Hn + b0 * Hn + k];
        h_sh[0][0][k] = h0[dir * Bn * Hn + b0 * Hn + k];
    } else if (g == 1) {
        c = c0[dir * Bn * Hn + (b0 + 1) * Hn + k];
        h_sh[0][1][k] = h0[dir * Bn * Hn + (b0 + 1) * Hn + k];
    }

    const float bias = g_bias[col];
    const int tstep = dir ? -1 : 1;
    int t = dir ? (Sn - 1) : 0;
    const int ib0 = b0 * Sn, ib1 = (b0 + 1) * Sn;

    // synchronous x for step 0
    float x0, x1;
    {
        int s = t;
        x0 = bias + g_proj[(size_t)wi[ib0 + s] * 512 + col]
                  + g_proj[(size_t)(20000 + fi[ib0 + s]) * 512 + col]
                  + g_proj[(size_t)(20060 + bi[ib0 + s]) * 512 + col]
                  + g_proj[(size_t)(20068 + ri[ib0 + s]) * 512 + col]
                  + g_proj[(size_t)(20368 + pi[ib0 + s]) * 512 + col];
        x1 = bias + g_proj[(size_t)wi[ib1 + s] * 512 + col]
                  + g_proj[(size_t)(20000 + fi[ib1 + s]) * 512 + col]
                  + g_proj[(size_t)(20060 + bi[ib1 + s]) * 512 + col]
                  + g_proj[(size_t)(20068 + ri[ib1 + s]) * 512 + col]
                  + g_proj[(size_t)(20368 + pi[ib1 + s]) * 512 + col];
    }
    // ids for step 1
    int idw0 = 0, idf0 = 0, idb0 = 0, idr0 = 0, idp0 = 0;
    int idw1 = 0, idf1 = 0, idb1 = 0, idr1 = 0, idp1 = 0;
    {
        int s = t + tstep;
        idw0 = wi[ib0 + s]; idf0 = fi[ib0 + s]; idb0 = bi[ib0 + s]; idr0 = ri[ib0 + s]; idp0 = pi[ib0 + s];
        idw1 = wi[ib1 + s]; idf1 = fi[ib1 + s]; idb1 = bi[ib1 + s]; idr1 = ri[ib1 + s]; idp1 = pi[ib1 + s];
    }

    __syncthreads();
    int pbuf = 0;
    const int q4 = (threadIdx.x & 31) & ~3;

    for (int step = 0; step < Sn; step++) {
        // issue proj loads for step+1 (ids fetched last iteration)
        float n00 = 0.f, n01 = 0.f, n02 = 0.f, n03 = 0.f, n04 = 0.f;
        float n10 = 0.f, n11 = 0.f, n12 = 0.f, n13 = 0.f, n14 = 0.f;
        if (step + 1 < Sn) {
            n00 = g_proj[(size_t)idw0 * 512 + col];
            n01 = g_proj[(size_t)(20000 + idf0) * 512 + col];
            n02 = g_proj[(size_t)(20060 + idb0) * 512 + col];
            n03 = g_proj[(size_t)(20068 + idr0) * 512 + col];
            n04 = g_proj[(size_t)(20368 + idp0) * 512 + col];
            n10 = g_proj[(size_t)idw1 * 512 + col];
            n11 = g_proj[(size_t)(20000 + idf1) * 512 + col];
            n12 = g_proj[(size_t)(20060 + idb1) * 512 + col];
            n13 = g_proj[(size_t)(20068 + idr1) * 512 + col];
            n14 = g_proj[(size_t)(20368 + idp1) * 512 + col];
        }
        // fetch ids for step+2
        if (step + 2 < Sn) {
            int s2 = t + 2 * tstep;
            idw0 = wi[ib0 + s2]; idf0 = fi[ib0 + s2]; idb0 = bi[ib0 + s2]; idr0 = ri[ib0 + s2]; idp0 = pi[ib0 + s2];
            idw1 = wi[ib1 + s2]; idf1 = fi[ib1 + s2]; idb1 = bi[ib1 + s2]; idr1 = ri[ib1 + s2]; idp1 = pi[ib1 + s2];
        }

        // matvec: z = x + W_row . h  (both batches, 2 chains each)
        unsigned long long a00 = 0ull, a01 = 0ull, a10 = 0ull, a11 = 0ull;
        const ulonglong2* hp0 = (const ulonglong2*)h_sh[pbuf][0];
        const ulonglong2* hp1 = (const ulonglong2*)h_sh[pbuf][1];
#pragma unroll
        for (int q = 0; q < 16; q++) {
            ulonglong2 v0 = hp0[q], v1 = hp1[q];
            fma2(a00, v0.x, wp[2 * q]); fma2(a01, v0.y, wp[2 * q + 1]);
            fma2(a10, v1.x, wp[2 * q]); fma2(a11, v1.y, wp[2 * q + 1]);
        }
        float2 u00 = unpack2(a00), u01 = unpack2(a01);
        float2 u10 = unpack2(a10), u11 = unpack2(a11);
        float z0 = x0 + (u00.x + u00.y) + (u01.x + u01.y);
        float z1 = x1 + (u10.x + u10.y) + (u11.x + u11.y);

        // quad shfl: gate order i(0) f(1) g(2) o(3)
        float zA1 = __shfl_sync(FULL, z0, q4 + 1, 32);
        float zA2 = __shfl_sync(FULL, z0, q4 + 2, 32);
        float zA3 = __shfl_sync(FULL, z0, q4 + 3, 32);
        float zB0 = __shfl_sync(FULL, z1, q4 + 0, 32);
        float zB2 = __shfl_sync(FULL, z1, q4 + 2, 32);
        float zB3 = __shfl_sync(FULL, z1, q4 + 3, 32);

        if (g == 0) {           // batch 0: zi=z0, zf=zA1, zg=zA2, zo=zA3
            c = sigfast(zA1) * c + sigfast(z0) * tanhfast(zA2);
            float hh = sigfast(zA3) * tanhfast(c);
            h_sh[pbuf ^ 1][0][k] = hh;
            hout[((size_t)t * Bn + b0) * Hn + k] = hh;
        } else if (g == 1) {    // batch 1: zi=zB0, zf=z1, zg=zB2, zo=zB3
            c = sigfast(z1) * c + sigfast(zB0) * tanhfast(zB2);
            float hh = sigfast(zB3) * tanhfast(c);
            h_sh[pbuf ^ 1][1][k] = hh;
            hout[((size_t)t * Bn + b0 + 1) * Hn + k] = hh;
        }
        __syncthreads();

        x0 = bias + n00 + n01 + n02 + n03 + n04;
        x1 = bias + n10 + n11 + n12 + n13 + n14;
        pbuf ^= 1;
        t += tstep;
    }
}

// ---- K4: emissions, SMEM-staged, 32 positions per 512-thread block ----
__global__ __launch_bounds__(512)
void feats_kernel(const float* __restrict__ Wout, const float* __restrict__ bout) {
    const int p0 = blockIdx.x * 32;
    const int tid = threadIdx.x;
    __shared__ __align__(16) float hs[32][132];
    __shared__ __align__(16) float ws[16 * 132];
    __shared__ float bs[16];

    {
        int f = tid * 4;
        if (f < 2048) {
            float4 w4 = *(const float4*)(Wout + f);
            int row = f >> 7, off = f & 127;
            *(float4*)&ws[row * 132 + off] = w4;
        }
        if (tid < 16) bs[tid] = bout[tid];
    }
    {
        int f = tid * 4;
        float4 hf4 = *(const float4*)(g_h[0] + (size_t)p0 * Hn + f);
        float4 hb4 = *(const float4*)(g_h[1] + (size_t)p0 * Hn + f);
        int pos = f >> 6, off = f & 63;
        *(float4*)&hs[pos][off] = hf4;
        *(float4*)&hs[pos][64 + off] = hb4;
    }
    __syncthreads();

    const int pos = tid >> 4, tag = tid & 15;
    const float4* hv = (const float4*)&hs[pos][0];
    const float4* wv = (const float4*)&ws[tag * 132];
    float acc0 = bs[tag], acc1 = 0.f;
#pragma unroll
    for (int kq = 0; kq < 32; kq += 2) {
        float4 a = hv[kq], b = wv[kq];
        float4 a2 = hv[kq + 1], b2 = wv[kq + 1];
        acc0 = fmaf(a.x, b.x, fmaf(a.y, b.y, acc0));
        acc1 = fmaf(a.z, b.z, fmaf(a.w, b.w, acc1));
        acc0 = fmaf(a2.x, b2.x, fmaf(a2.y, b2.y, acc0));
        acc1 = fmaf(a2.z, b2.z, fmaf(a2.w, b2.w, acc1));
    }
    g_feats[(size_t)(p0 + pos) * Tn + tag] = acc0 + acc1;
}

// ---- K5: CRF forward + real path -> loss ----
__global__ __launch_bounds__(32)
void crf_kernel(const float* __restrict__ transitions,
                const int* __restrict__ tags, float* __restrict__ out) {
    const int b = blockIdx.x * 2 + (threadIdx.x >> 4);
    const int n = threadIdx.x & 15;
    const unsigned FULL = 0xFFFFFFFFu;

    float expT[16];
#pragma unroll
    for (int kq = 0; kq < 16; kq++) expT[kq] = __expf(transitions[n * 16 + kq]);

    float alpha = g_feats[(size_t)b * Tn + n] + transitions[n * 16 + START_IX];
    float feat = g_feats[((size_t)1 * Bn + b) * Tn + n];

    for (int s = 1; s < Sn; s++) {
        float feat_nx = 0.f;
        if (s + 1 < Sn) feat_nx = g_feats[((size_t)(s + 1) * Bn + b) * Tn + n];
        float m = __shfl_sync(FULL, alpha, 0, 16);
        float e = __expf(alpha - m);
        float acc_a = 0.f, acc_b = 0.f;
#pragma unroll
        for (int kq = 0; kq < 16; kq += 2) {
            acc_a = fmaf(__shfl_sync(FULL, e, kq, 16), expT[kq], acc_a);
            acc_b = fmaf(__shfl_sync(FULL, e, kq + 1, 16), expT[kq + 1], acc_b);
        }
        alpha = feat + m + __logf(acc_a + acc_b);
        feat = feat_nx;
    }
    float v = alpha + transitions[STOP_IX * 16 + n];
    float m2 = v;
#pragma unroll
    for (int o = 8; o; o >>= 1) m2 = fmaxf(m2, __shfl_xor_sync(FULL, m2, o, 16));
    float se = __expf(v - m2);
#pragma unroll
    for (int o = 8; o; o >>= 1) se += __shfl_xor_sync(FULL, se, o, 16);
    float all_sc = m2 + __logf(se);

    float rp = 0.f;
    for (int s = n; s < Sn; s += 16) {
        int tg = tags[b * Sn + s];
        int pv = (s == 0) ? START_IX : tags[b * Sn + s - 1];
        rp += g_feats[((size_t)s * Bn + b) * Tn + tg] + transitions[tg * 16 + pv];
    }
#pragma unroll
    for (int o = 8; o; o >>= 1) rp += __shfl_xor_sync(FULL, rp, o, 16);

    if (n == 0) {
        float real = rp + transitions[STOP_IX * 16 + tags[b * Sn + Sn - 1]];
        out[b] = all_sc - real;
    }
}

extern "C" void kernel_launch(void* const* d_in, const int* in_sizes, int n_in,
                              void* d_out, int out_size) {
    const float* word_emb    = (const float*)d_in[0];
    const float* flag_emb    = (const float*)d_in[1];
    const float* bound_emb   = (const float*)d_in[2];
    const float* radical_emb = (const float*)d_in[3];
    const float* pinyin_emb  = (const float*)d_in[4];
    const float* Wih_f = (const float*)d_in[5];
    const float* Whh_f = (const float*)d_in[6];
    const float* bih_f = (const float*)d_in[7];
    const float* bhh_f = (const float*)d_in[8];
    const float* Wih_b = (const float*)d_in[9];
    const float* Whh_b = (const float*)d_in[10];
    const float* bih_b = (const float*)d_in[11];
    const float* bhh_b = (const float*)d_in[12];
    const float* Wout  = (const float*)d_in[13];
    const float* bout  = (const float*)d_in[14];
    const float* transitions = (const float*)d_in[15];
    const float* h0 = (const float*)d_in[16];
    const float* c0 = (const float*)d_in[17];
    const int* word_ids    = (const int*)d_in[18];
    const int* flag_ids    = (const int*)d_in[19];
    const int* bound_ids   = (const int*)d_in[20];
    const int* radical_ids = (const int*)d_in[21];
    const int* pinyin_ids  = (const int*)d_in[22];
    const int* tags        = (const int*)d_in[23];

    prep_kernel<<<(En * 512 + 255) / 256, 256>>>(Wih_f, Wih_b, bih_f, bhh_f, bih_b, bhh_b);

    proj_all_kernel<<<2610, 512>>>(word_emb, flag_emb, bound_emb, radical_emb, pinyin_emb);

    dim3 lgrid(128, 2);
    lstm_kernel<<<lgrid, 256>>>(Whh_f, Whh_b, h0, c0,
                                word_ids, flag_ids, bound_ids, radical_ids, pinyin_ids);

    feats_kernel<<<Sn * Bn / 32, 512>>>(Wout, bout);

    crf_kernel<<<Bn / 2, 32>>>(transitions, tags, (float*)d_out);
}

// round 7
// speedup vs baseline: 1.2283x; 1.2283x over previous
#include <cuda_runtime.h>
#include <cstdint>
#include <math.h>

#define Bn 256
#define Sn 512
#define Hn 64
#define En 330
#define Tn 16
#define Gn 256   // 4H
#define START_IX 14
#define STOP_IX 15
#define NROWS_TOTAL 20868

// ---- scratch (static device memory) ----
__device__ float g_WT[En * 512];                       // Wih transposed+concat [E][512]
__device__ float g_bias[512];
__device__ float g_proj[(size_t)NROWS_TOTAL * 512];    // projected tables  ~42.7MB
__device__ float g_xp[2][(size_t)Sn * Bn * Gn];        // x-projections     2x134MB
__device__ float g_h[2][(size_t)Sn * Bn * Hn];         // lstm hidden       2x33.5MB
__device__ float g_feats[(size_t)Sn * Bn * Tn];        // emissions         8.4MB

// ---- packed f32x2 helpers ----
__device__ __forceinline__ void fma2(unsigned long long& d, unsigned long long a,
                                     unsigned long long b) {
    asm("fma.rn.f32x2 %0, %1, %2, %0;" : "+l"(d) : "l"(a), "l"(b));
}
__device__ __forceinline__ unsigned long long pack2(float a, float b) {
    unsigned long long v;
    asm("mov.b64 %0, {%1,%2};" : "=l"(v) : "f"(a), "f"(b));
    return v;
}
__device__ __forceinline__ float2 unpack2(unsigned long long v) {
    float2 r;
    asm("mov.b64 {%0,%1}, %2;" : "=f"(r.x), "=f"(r.y) : "l"(v));
    return r;
}
__device__ __forceinline__ float tanhfast(float x) {
    float y;
    asm("tanh.approx.f32 %0, %1;" : "=f"(y) : "f"(x));
    return y;
}
__device__ __forceinline__ float sigfast(float x) {
    return fmaf(0.5f, tanhfast(0.5f * x), 0.5f);
}

// ---- K0: transpose Wih_f/Wih_b into [E][512] and fold biases ----
__global__ void prep_kernel(const float* __restrict__ Wf, const float* __restrict__ Wb,
                            const float* __restrict__ bihf, const float* __restrict__ bhhf,
                            const float* __restrict__ bihb, const float* __restrict__ bhhb) {
    int idx = blockIdx.x * blockDim.x + threadIdx.x;
    if (idx < En * 512) {
        int c = idx / 512, j = idx % 512;
        g_WT[idx] = (j < 256) ? Wf[j * En + c] : Wb[(j - 256) * En + c];
    }
    if (idx < 512) {
        g_bias[idx] = (idx < 256) ? (bihf[idx] + bhhf[idx]) : (bihb[idx - 256] + bhhb[idx - 256]);
    }
}

// ---- K1: project ALL embedding tables into g_proj (single launch) ----
__global__ __launch_bounds__(512)
void proj_all_kernel(const float* __restrict__ word, const float* __restrict__ flag,
                     const float* __restrict__ bound, const float* __restrict__ radical,
                     const float* __restrict__ pinyin) {
    const int bb = blockIdx.x;
    const float* emb;
    int nrows, width, segoff, base, r0;
    if (bb < 2500)      { emb = word;    nrows = 20000; width = 100; segoff = 0;   base = 0;     r0 = bb * 8; }
    else if (bb < 2508) { emb = flag;    nrows = 60;    width = 50;  segoff = 100; base = 20000; r0 = (bb - 2500) * 8; }
    else if (bb < 2509) { emb = bound;   nrows = 8;     width = 50;  segoff = 150; base = 20060; r0 = 0; }
    else if (bb < 2547) { emb = radical; nrows = 300;   width = 50;  segoff = 200; base = 20068; r0 = (bb - 2509) * 8; }
    else                { emb = pinyin;  nrows = 500;   width = 80;  segoff = 250; base = 20368; r0 = (bb - 2547) * 8; }

    const int j = threadIdx.x;             // output column 0..511
    __shared__ __align__(16) float es[8][112];
    for (int i = threadIdx.x; i < 8 * width; i += 512) {
        int rr = i / width, kk = i % width;
        es[rr][kk] = (r0 + rr < nrows) ? emb[(size_t)(r0 + rr) * width + kk] : 0.f;
    }
    __syncthreads();

    unsigned long long acc[8] = {0ull, 0ull, 0ull, 0ull, 0ull, 0ull, 0ull, 0ull};
    const int hw = width >> 1;
    for (int kk = 0; kk < hw; kk++) {
        float w0 = g_WT[(size_t)(segoff + 2 * kk) * 512 + j];
        float w1 = g_WT[(size_t)(segoff + 2 * kk + 1) * 512 + j];
        unsigned long long w2 = pack2(w0, w1);
#pragma unroll
        for (int r = 0; r < 8; r++) {
            unsigned long long h2 = *(const unsigned long long*)&es[r][2 * kk];
            fma2(acc[r], h2, w2);
        }
    }
#pragma unroll
    for (int r = 0; r < 8; r++) {
        if (r0 + r < nrows) {
            float2 u = unpack2(acc[r]);
            g_proj[(size_t)(base + r0 + r) * 512 + j] = u.x + u.y;
        }
    }
}

// ---- K2: gather-sum, float4 vectorized, 4 positions per block ----
__global__ __launch_bounds__(128)
void gather_kernel(const int* __restrict__ wi, const int* __restrict__ fi,
                   const int* __restrict__ bi, const int* __restrict__ ri,
                   const int* __restrict__ pi) {
    const int t = threadIdx.x;             // 0..127, covers float4 lane
    const float4 bias4 = *(const float4*)(g_bias + 4 * t);
#pragma unroll
    for (int pos = 0; pos < 4; pos++) {
        const int sb = blockIdx.x * 4 + pos;   // sb = s*B + b
        const int s = sb >> 8, b = sb & 255;
        const int iw  = wi[b * Sn + s];
        const int ifl = fi[b * Sn + s];
        const int ib  = bi[b * Sn + s];
        const int ir  = ri[b * Sn + s];
        const int ip  = pi[b * Sn + s];
        float4 v = bias4;
        float4 a0 = *(const float4*)(g_proj + (size_t)iw * 512 + 4 * t);
        float4 a1 = *(const float4*)(g_proj + (size_t)(20000 + ifl) * 512 + 4 * t);
        float4 a2 = *(const float4*)(g_proj + (size_t)(20060 + ib) * 512 + 4 * t);
        float4 a3 = *(const float4*)(g_proj + (size_t)(20068 + ir) * 512 + 4 * t);
        float4 a4 = *(const float4*)(g_proj + (size_t)(20368 + ip) * 512 + 4 * t);
        v.x += a0.x + a1.x + a2.x + a3.x + a4.x;
        v.y += a0.y + a1.y + a2.y + a3.y + a4.y;
        v.z += a0.z + a1.z + a2.z + a3.z + a4.z;
        v.w += a0.w + a1.w + a2.w + a3.w + a4.w;
        if (t < 64) *(float4*)(g_xp[0] + (size_t)sb * Gn + 4 * t) = v;
        else        *(float4*)(g_xp[1] + (size_t)sb * Gn + 4 * t - 256) = v;
    }
}

// ---- K3: recurrence, quad-gate layout. grid (128,2), 256 thr, Bc=2 ----
// thread j -> cell k=j>>2, gate g=j&3, Whh row = g*64+k.
// x from g_xp (prefetched); z exchanged via quad shfl; ONE barrier per step.
__global__ __launch_bounds__(256, 2)
void lstm_kernel(const float* __restrict__ Whh_f, const float* __restrict__ Whh_b,
                 const float* __restrict__ h0, const float* __restrict__ c0) {
    const int dir = blockIdx.y;
    const int b0 = blockIdx.x * 2;
    const float* __restrict__ Whh = dir ? Whh_b : Whh_f;
    const float* __restrict__ xp = g_xp[dir];
    float* __restrict__ hout = g_h[dir];
    const unsigned FULL = 0xFFFFFFFFu;

    const int j = threadIdx.x;
    const int k = j >> 2, g = j & 3;
    const int row = g * 64 + k;

    // weight row, k-paired
    unsigned long long wp[32];
    {
        const ulonglong2* wrow = (const ulonglong2*)(Whh + row * 64);
#pragma unroll
        for (int q = 0; q < 16; q++) { ulonglong2 t2 = wrow[q]; wp[2 * q] = t2.x; wp[2 * q + 1] = t2.y; }
    }

    __shared__ __align__(16) float h_sh[2][2][64];   // [buf][batch][cell]

    float c = 0.f;
    if (g == 0) {
        c = c0[dir * Bn * Hn + b0 * Hn + k];
        h_sh[0][0][k] = h0[dir * Bn * Hn + b0 * Hn + k];
    } else if (g == 1) {
        c = c0[dir * Bn * Hn + (b0 + 1) * Hn + k];
        h_sh[0][1][k] = h0[dir * Bn * Hn + (b0 + 1) * Hn + k];
    }

    const int tstep = dir ? -1 : 1;
    int t = dir ? (Sn - 1) : 0;

    const float* xr = xp + ((size_t)t * Bn + b0) * Gn + row;
    float x0 = xr[0], x1 = xr[Gn];
    __syncthreads();

    int pbuf = 0;
    const int q4 = (threadIdx.x & 31) & ~3;

    for (int step = 0; step < Sn; step++) {
        // prefetch next step's x
        float xn0 = 0.f, xn1 = 0.f;
        if (step + 1 < Sn) {
            const float* xn = xp + ((size_t)(t + tstep) * Bn + b0) * Gn + row;
            xn0 = xn[0]; xn1 = xn[Gn];
        }

        // matvec: z = x + W_row . h  (both batches, 2 chains each)
        unsigned long long a00 = 0ull, a01 = 0ull, a10 = 0ull, a11 = 0ull;
        const ulonglong2* hp0 = (const ulonglong2*)h_sh[pbuf][0];
        const ulonglong2* hp1 = (const ulonglong2*)h_sh[pbuf][1];
#pragma unroll
        for (int q = 0; q < 16; q++) {
            ulonglong2 v0 = hp0[q], v1 = hp1[q];
            fma2(a00, v0.x, wp[2 * q]); fma2(a01, v0.y, wp[2 * q + 1]);
            fma2(a10, v1.x, wp[2 * q]); fma2(a11, v1.y, wp[2 * q + 1]);
        }
        float2 u00 = unpack2(a00), u01 = unpack2(a01);
        float2 u10 = unpack2(a10), u11 = unpack2(a11);
        float z0 = x0 + (u00.x + u00.y) + (u01.x + u01.y);
        float z1 = x1 + (u10.x + u10.y) + (u11.x + u11.y);

        // quad shfl exchange: gate order i(0) f(1) g(2) o(3)
        float zA1 = __shfl_sync(FULL, z0, q4 + 1, 32);
        float zA2 = __shfl_sync(FULL, z0, q4 + 2, 32);
        float zA3 = __shfl_sync(FULL, z0, q4 + 3, 32);
        float zB0 = __shfl_sync(FULL, z1, q4 + 0, 32);
        float zB2 = __shfl_sync(FULL, z1, q4 + 2, 32);
        float zB3 = __shfl_sync(FULL, z1, q4 + 3, 32);

        if (g == 0) {           // batch 0: zi=z0, zf=zA1, zg=zA2, zo=zA3
            c = sigfast(zA1) * c + sigfast(z0) * tanhfast(zA2);
            float hh = sigfast(zA3) * tanhfast(c);
            h_sh[pbuf ^ 1][0][k] = hh;
            hout[((size_t)t * Bn + b0) * Hn + k] = hh;
        } else if (g == 1) {    // batch 1: zi=zB0, zf=z1, zg=zB2, zo=zB3
            c = sigfast(z1) * c + sigfast(zB0) * tanhfast(zB2);
            float hh = sigfast(zB3) * tanhfast(c);
            h_sh[pbuf ^ 1][1][k] = hh;
            hout[((size_t)t * Bn + b0 + 1) * Hn + k] = hh;
        }
        __syncthreads();

        x0 = xn0; x1 = xn1;
        pbuf ^= 1;
        t += tstep;
    }
}

// ---- K4: emissions, SMEM-staged, 32 positions per 512-thread block ----
__global__ __launch_bounds__(512)
void feats_kernel(const float* __restrict__ Wout, const float* __restrict__ bout) {
    const int p0 = blockIdx.x * 32;
    const int tid = threadIdx.x;
    __shared__ __align__(16) float hs[32][132];
    __shared__ __align__(16) float ws[16 * 132];
    __shared__ float bs[16];

    {
        int f = tid * 4;
        if (f < 2048) {
            float4 w4 = *(const float4*)(Wout + f);
            int row = f >> 7, off = f & 127;
            *(float4*)&ws[row * 132 + off] = w4;
        }
        if (tid < 16) bs[tid] = bout[tid];
    }
    {
        int f = tid * 4;
        float4 hf4 = *(const float4*)(g_h[0] + (size_t)p0 * Hn + f);
        float4 hb4 = *(const float4*)(g_h[1] + (size_t)p0 * Hn + f);
        int pos = f >> 6, off = f & 63;
        *(float4*)&hs[pos][off] = hf4;
        *(float4*)&hs[pos][64 + off] = hb4;
    }
    __syncthreads();

    const int pos = tid >> 4, tag = tid & 15;
    const float4* hv = (const float4*)&hs[pos][0];
    const float4* wv = (const float4*)&ws[tag * 132];
    float acc0 = bs[tag], acc1 = 0.f;
#pragma unroll
    for (int kq = 0; kq < 32; kq += 2) {
        float4 a = hv[kq], b = wv[kq];
        float4 a2 = hv[kq + 1], b2 = wv[kq + 1];
        acc0 = fmaf(a.x, b.x, fmaf(a.y, b.y, acc0));
        acc1 = fmaf(a.z, b.z, fmaf(a.w, b.w, acc1));
        acc0 = fmaf(a2.x, b2.x, fmaf(a2.y, b2.y, acc0));
        acc1 = fmaf(a2.z, b2.z, fmaf(a2.w, b2.w, acc1));
    }
    g_feats[(size_t)(p0 + pos) * Tn + tag] = acc0 + acc1;
}

// ---- K5: CRF forward + real path -> loss ----
__global__ __launch_bounds__(32)
void crf_kernel(const float* __restrict__ transitions,
                const int* __restrict__ tags, float* __restrict__ out) {
    const int b = blockIdx.x * 2 + (threadIdx.x >> 4);
    const int n = threadIdx.x & 15;
    const unsigned FULL = 0xFFFFFFFFu;

    float expT[16];
#pragma unroll
    for (int kq = 0; kq < 16; kq++) expT[kq] = __expf(transitions[n * 16 + kq]);

    float alpha = g_feats[(size_t)b * Tn + n] + transitions[n * 16 + START_IX];
    float feat = g_feats[((size_t)1 * Bn + b) * Tn + n];

    for (int s = 1; s < Sn; s++) {
        float feat_nx = 0.f;
        if (s + 1 < Sn) feat_nx = g_feats[((size_t)(s + 1) * Bn + b) * Tn + n];
        float m = __shfl_sync(FULL, alpha, 0, 16);
        float e = __expf(alpha - m);
        float acc_a = 0.f, acc_b = 0.f;
#pragma unroll
        for (int kq = 0; kq < 16; kq += 2) {
            acc_a = fmaf(__shfl_sync(FULL, e, kq, 16), expT[kq], acc_a);
            acc_b = fmaf(__shfl_sync(FULL, e, kq + 1, 16), expT[kq + 1], acc_b);
        }
        alpha = feat + m + __logf(acc_a + acc_b);
        feat = feat_nx;
    }
    float v = alpha + transitions[STOP_IX * 16 + n];
    float m2 = v;
#pragma unroll
    for (int o = 8; o; o >>= 1) m2 = fmaxf(m2, __shfl_xor_sync(FULL, m2, o, 16));
    float se = __expf(v - m2);
#pragma unroll
    for (int o = 8; o; o >>= 1) se += __shfl_xor_sync(FULL, se, o, 16);
    float all_sc = m2 + __logf(se);

    float rp = 0.f;
    for (int s = n; s < Sn; s += 16) {
        int tg = tags[b * Sn + s];
        int pv = (s == 0) ? START_IX : tags[b * Sn + s - 1];
        rp += g_feats[((size_t)s * Bn + b) * Tn + tg] + transitions[tg * 16 + pv];
    }
#pragma unroll
    for (int o = 8; o; o >>= 1) rp += __shfl_xor_sync(FULL, rp, o, 16);

    if (n == 0) {
        float real = rp + transitions[STOP_IX * 16 + tags[b * Sn + Sn - 1]];
        out[b] = all_sc - real;
    }
}

extern "C" void kernel_launch(void* const* d_in, const int* in_sizes, int n_in,
                              void* d_out, int out_size) {
    const float* word_emb    = (const float*)d_in[0];
    const float* flag_emb    = (const float*)d_in[1];
    const float* bound_emb   = (const float*)d_in[2];
    const float* radical_emb = (const float*)d_in[3];
    const float* pinyin_emb  = (const float*)d_in[4];
    const float* Wih_f = (const float*)d_in[5];
    const float* Whh_f = (const float*)d_in[6];
    const float* bih_f = (const float*)d_in[7];
    const float* bhh_f = (const float*)d_in[8];
    const float* Wih_b = (const float*)d_in[9];
    const float* Whh_b = (const float*)d_in[10];
    const float* bih_b = (const float*)d_in[11];
    const float* bhh_b = (const float*)d_in[12];
    const float* Wout  = (const float*)d_in[13];
    const float* bout  = (const float*)d_in[14];
    const float* transitions = (const float*)d_in[15];
    const float* h0 = (const float*)d_in[16];
    const float* c0 = (const float*)d_in[17];
    const int* word_ids    = (const int*)d_in[18];
    const int* flag_ids    = (const int*)d_in[19];
    const int* bound_ids   = (const int*)d_in[20];
    const int* radical_ids = (const int*)d_in[21];
    const int* pinyin_ids  = (const int*)d_in[22];
    const int* tags        = (const int*)d_in[23];

    prep_kernel<<<(En * 512 + 255) / 256, 256>>>(Wih_f, Wih_b, bih_f, bhh_f, bih_b, bhh_b);

    proj_all_kernel<<<2610, 512>>>(word_emb, flag_emb, bound_emb, radical_emb, pinyin_emb);

    gather_kernel<<<Sn * Bn / 4, 128>>>(word_ids, flag_ids, bound_ids, radical_ids, pinyin_ids);

    dim3 lgrid(128, 2);
    lstm_kernel<<<lgrid, 256>>>(Whh_f, Whh_b, h0, c0);

    feats_kernel<<<Sn * Bn / 32, 512>>>(Wout, bout);

    crf_kernel<<<Bn / 2, 32>>>(transitions, tags, (float*)d_out);
}